// round 15
// baseline (speedup 1.0000x reference)
#include <cuda_runtime.h>
#include <cuda_bf16.h>
#include <math.h>
#include <stdint.h>

#define Nn 20000
#define Ee 40000
#define Bb 1000
#define Ff 32
#define Dd 64
#define HE 128
#define DDm 4096

// ---------------- scratch ----------------
__device__ float g_h[Nn * Dd];
__device__ __nv_bfloat16 g_Wb[DDm * HE];
__device__ __nv_bfloat16 g_We[(size_t)Ee * DDm];
__device__ float g_agg[Nn * Dd];   // starts zeroed; every call leaves it zeroed again
__device__ float g_deg[Nn];
__device__ int   g_seg[Bb + 1];

// transposed weights [k][row]
__device__ float g_Wt0[Ff * Dd];
__device__ float g_Wti[Dd * 3 * Dd];
__device__ float g_Wth[Dd * 3 * Dd];
__device__ float g_Wtil[2 * Dd * 4 * Dd];
__device__ float g_Wthl[Dd * 4 * Dd];
__device__ float g_Wt1[2 * Dd * Dd];

__device__ __forceinline__ float sigf(float v) { return 1.0f / (1.0f + expf(-v)); }

// ---------------- setup 1: transpose + zero_deg + cvtW ----------------
__global__ void k_setup1(const float* __restrict__ W0, const float* __restrict__ W_ih,
                         const float* __restrict__ W_hh, const float* __restrict__ W_ihl,
                         const float* __restrict__ W_hhl, const float* __restrict__ W1,
                         const float* __restrict__ We2) {
    int i = blockIdx.x * blockDim.x + threadIdx.x;
    if (i < 2048) { int r = i / 32, k = i % 32; g_Wt0[k * 64 + r] = W0[i]; return; }
    i -= 2048;
    if (i < 12288) { int r = i / 64, k = i % 64; g_Wti[k * 192 + r] = W_ih[i]; return; }
    i -= 12288;
    if (i < 12288) { int r = i / 64, k = i % 64; g_Wth[k * 192 + r] = W_hh[i]; return; }
    i -= 12288;
    if (i < 32768) { int r = i / 128, k = i % 128; g_Wtil[k * 256 + r] = W_ihl[i]; return; }
    i -= 32768;
    if (i < 16384) { int r = i / 64, k = i % 64; g_Wthl[k * 256 + r] = W_hhl[i]; return; }
    i -= 16384;
    if (i < 8192) { int r = i / 128, k = i % 128; g_Wt1[k * 64 + r] = W1[i]; return; }
    i -= 8192;
    if (i < Nn) { g_deg[i] = 0.0f; return; }
    i -= Nn;
    if (i < DDm * HE) g_Wb[i] = __float2bfloat16(We2[i]);
}
#define SETUP1_N (83968 + Nn + DDm * HE)

// ---------------- lin0 (4 nodes/block) + degree count + segment starts ----------------
#define LIN0_BLKS 5000
__global__ void k_lin0cs(const float* __restrict__ x, const float* __restrict__ b0,
                         const int* __restrict__ ei, const int* __restrict__ batch) {
    int bid = blockIdx.x;
    int t = threadIdx.x;
    if (bid < LIN0_BLKS) {
        int n = bid * 4 + (t >> 6);
        int c = t & 63;
        __shared__ float sx[4][Ff];
        if (c < Ff) sx[t >> 6][c] = x[n * Ff + c];
        __syncthreads();
        float acc = b0[c];
#pragma unroll 8
        for (int k = 0; k < Ff; k++) acc += sx[t >> 6][k] * g_Wt0[k * 64 + c];
        g_h[n * Dd + c] = fmaxf(acc, 0.0f);
        return;
    }
    bid -= LIN0_BLKS;
    if (bid < 157) {
        int e = bid * 256 + t;
        if (e < Ee) atomicAdd(&g_deg[ei[Ee + e]], 1.0f);
    } else {
        int b = (bid - 157) * 256 + t;
        if (b > Bb) return;
        int lo = 0, hi = Nn;
        while (lo < hi) {
            int mid = (lo + hi) >> 1;
            if (batch[mid] < b) lo = mid + 1; else hi = mid;
        }
        g_seg[b] = lo;
    }
}

// ---------------- HMMA GEMM v4: single B buffer, 2 blocks/SM ----------------
#define SPAD 136
#define CTILES 16
__global__ void __launch_bounds__(256, 2) k_gemm_tc2(const float* __restrict__ be2,
                                                     const float* __restrict__ ea,
                                                     const float* __restrict__ We1,
                                                     const float* __restrict__ be1) {
    extern __shared__ __nv_bfloat16 smem[];
    __nv_bfloat16* As = smem;                    // [128][SPAD]
    __nv_bfloat16* Bs = smem + 128 * SPAD;       // [128][SPAD]
    __shared__ float sea[128 * 5];
    __shared__ float sW1[128 * 5];
    __shared__ float sbe1[128];
    int row0 = blockIdx.x * 128;
    int colBase = blockIdx.y * (CTILES * 128);
    int tid = threadIdx.x;

    for (int idx = tid; idx < 640; idx += 256) {
        int r = idx / 5;
        sea[idx] = (row0 + r < Ee) ? ea[(size_t)(row0 + r) * 5 + (idx % 5)] : 0.0f;
        sW1[idx] = We1[idx];
    }
    if (tid < 128) sbe1[tid] = be1[tid];

    // prefetch B tile 0 (async; waited before first MMA)
    for (int idx = tid; idx < 2048; idx += 256) {
        int r = idx >> 4, c = (idx & 15) * 8;
        const __nv_bfloat16* src = &g_Wb[(size_t)(colBase + r) * HE + c];
        uint32_t daddr = (uint32_t)__cvta_generic_to_shared(&Bs[r * SPAD + c]);
        asm volatile("cp.async.cg.shared.global [%0], [%1], 16;\n" :: "r"(daddr), "l"(src));
    }
    asm volatile("cp.async.commit_group;\n");
    __syncthreads();   // sea/sW1/sbe1 ready

    // compute A tile: H = relu(ea @ We1^T + be1), bf16 into As
    for (int idx = tid; idx < 2048; idx += 256) {
        int r = idx >> 4, c0 = (idx & 15) * 8;
        uint32_t pk[4];
#pragma unroll
        for (int cc = 0; cc < 8; cc += 2) {
            float a0 = sbe1[c0 + cc], a1 = sbe1[c0 + cc + 1];
#pragma unroll
            for (int j = 0; j < 5; j++) {
                float e = sea[r * 5 + j];
                a0 += e * sW1[(c0 + cc) * 5 + j];
                a1 += e * sW1[(c0 + cc + 1) * 5 + j];
            }
            __nv_bfloat162 bb = __float22bfloat162_rn(make_float2(fmaxf(a0, 0.f), fmaxf(a1, 0.f)));
            pk[cc >> 1] = *reinterpret_cast<uint32_t*>(&bb);
        }
        *(uint4*)&As[r * SPAD + c0] = *(uint4*)pk;
    }

    int wid = tid >> 5, lane = tid & 31;
    int wm = (wid >> 2) * 64;
    int wn = (wid & 3) * 32;
    int q = lane >> 3, r8 = lane & 7;

    for (int ct = 0; ct < CTILES; ct++) {
        int col0 = colBase + ct * 128;

        asm volatile("cp.async.wait_group 0;\n");
        __syncthreads();   // B ready (and As visible first iter; prev stores done)

        float acc[4][4][4];
#pragma unroll
        for (int i = 0; i < 4; i++)
#pragma unroll
            for (int j = 0; j < 4; j++)
#pragma unroll
                for (int c = 0; c < 4; c++) acc[i][j][c] = 0.0f;

#pragma unroll
        for (int k0 = 0; k0 < 128; k0 += 16) {
            uint32_t a[4][4];
            uint32_t b[4][2];
#pragma unroll
            for (int mi = 0; mi < 4; mi++) {
                int m = wm + mi * 16 + ((q & 1) * 8) + r8;
                int k = k0 + ((q >> 1) * 8);
                uint32_t addr = (uint32_t)__cvta_generic_to_shared(&As[m * SPAD + k]);
                asm volatile("ldmatrix.sync.aligned.m8n8.x4.shared.b16 {%0,%1,%2,%3}, [%4];"
                             : "=r"(a[mi][0]), "=r"(a[mi][1]), "=r"(a[mi][2]), "=r"(a[mi][3])
                             : "r"(addr));
            }
#pragma unroll
            for (int np = 0; np < 2; np++) {
                int n = wn + np * 16 + ((q >> 1) * 8) + r8;
                int k = k0 + ((q & 1) * 8);
                uint32_t addr = (uint32_t)__cvta_generic_to_shared(&Bs[n * SPAD + k]);
                asm volatile("ldmatrix.sync.aligned.m8n8.x4.shared.b16 {%0,%1,%2,%3}, [%4];"
                             : "=r"(b[np * 2][0]), "=r"(b[np * 2][1]),
                               "=r"(b[np * 2 + 1][0]), "=r"(b[np * 2 + 1][1])
                             : "r"(addr));
            }
#pragma unroll
            for (int mi = 0; mi < 4; mi++)
#pragma unroll
                for (int ni = 0; ni < 4; ni++) {
                    asm volatile(
                        "mma.sync.aligned.m16n8k16.row.col.f32.bf16.bf16.f32 "
                        "{%0,%1,%2,%3}, {%4,%5,%6,%7}, {%8,%9}, {%0,%1,%2,%3};"
                        : "+f"(acc[mi][ni][0]), "+f"(acc[mi][ni][1]),
                          "+f"(acc[mi][ni][2]), "+f"(acc[mi][ni][3])
                        : "r"(a[mi][0]), "r"(a[mi][1]), "r"(a[mi][2]), "r"(a[mi][3]),
                          "r"(b[ni][0]), "r"(b[ni][1]));
                }
        }
        __syncthreads();   // all warps done reading Bs

        // stage C (+bias, bf16) into Bs
#pragma unroll
        for (int mi = 0; mi < 4; mi++) {
            int rloc0 = wm + mi * 16 + (lane >> 2);
#pragma unroll
            for (int ni = 0; ni < 4; ni++) {
                int c = wn + ni * 8 + (lane & 3) * 2;
                float b0v = be2[col0 + c], b1v = be2[col0 + c + 1];
                *(__nv_bfloat162*)&Bs[rloc0 * SPAD + c] =
                    __float22bfloat162_rn(make_float2(acc[mi][ni][0] + b0v, acc[mi][ni][1] + b1v));
                *(__nv_bfloat162*)&Bs[(rloc0 + 8) * SPAD + c] =
                    __float22bfloat162_rn(make_float2(acc[mi][ni][2] + b0v, acc[mi][ni][3] + b1v));
            }
        }
        __syncthreads();

        // coalesced stores; then issue next B prefetch (same buffer, after stores read it)
        for (int idx = tid; idx < 2048; idx += 256) {
            int r = idx >> 4, c = (idx & 15) * 8;
            if (row0 + r < Ee)
                *(uint4*)&g_We[(size_t)(row0 + r) * DDm + col0 + c] = *(const uint4*)&Bs[r * SPAD + c];
        }
        __syncthreads();   // stores (reads of Bs) complete before refilling Bs

        if (ct + 1 < CTILES) {
            int coln = col0 + 128;
            for (int idx = tid; idx < 2048; idx += 256) {
                int r = idx >> 4, c = (idx & 15) * 8;
                const __nv_bfloat16* src = &g_Wb[(size_t)(coln + r) * HE + c];
                uint32_t daddr = (uint32_t)__cvta_generic_to_shared(&Bs[r * SPAD + c]);
                asm volatile("cp.async.cg.shared.global [%0], [%1], 16;\n" :: "r"(daddr), "l"(src));
            }
            asm volatile("cp.async.commit_group;\n");
        }
    }
}

// ---------------- message + scatter ----------------
__global__ void k_msg(const int* __restrict__ ei) {
    int w = threadIdx.x >> 5;
    int e = blockIdx.x * 8 + w;
    int lane = threadIdx.x & 31;
    __shared__ float ss[8][Dd];
    if (e >= Ee) return;
    int src = ei[e], dst = ei[Ee + e];
    ss[w][lane] = g_h[src * Dd + lane];
    ss[w][lane + 32] = g_h[src * Dd + 32 + lane];
    __syncwarp();
    const __nv_bfloat162* W = (const __nv_bfloat162*)(g_We + (size_t)e * DDm);
    float a0 = 0.f, a1 = 0.f;
#pragma unroll
    for (int i = 0; i < Dd; i++) {
        float si = ss[w][i];
        float2 wf = __bfloat1622float2(W[i * 32 + lane]);
        a0 += si * wf.x;
        a1 += si * wf.y;
    }
    atomicAdd(&g_agg[dst * Dd + 2 * lane], a0);
    atomicAdd(&g_agg[dst * Dd + 2 * lane + 1], a1);
}

// ---------------- GRU v5: 8 nodes/block, float4-packed smem, f32x2 FMA ----------------
__global__ void __launch_bounds__(384) k_gru5(const float* __restrict__ b_ih,
                                              const float* __restrict__ b_hh,
                                              const float* __restrict__ b_conv) {
    __shared__ float4 sp[2][128];
    __shared__ float pg[8][384];
    int t = threadIdx.x;
    int n0 = blockIdx.x * 8;

    for (int i = t; i < 1024; i += 384) {
        int node = i >> 7, j = i & 127;
        int n = n0 + node;
        float val;
        if (j < 64) {
            float dg = fmaxf(g_deg[n], 1.0f);
            val = fmaxf(g_agg[n * Dd + j] / dg + b_conv[j], 0.0f);
            g_agg[n * Dd + j] = 0.0f;
        } else {
            val = g_h[n * Dd + (j - 64)];
        }
        reinterpret_cast<float*>(&sp[node >> 2][j])[node & 3] = val;
    }
    __syncthreads();

    bool isI = (t < 192);
    int col = isI ? t : t - 192;
    const float* W = isI ? g_Wti : g_Wth;
    int off = isI ? 0 : 64;
    float bias = isI ? b_ih[col] : b_hh[col];

    double accd[4];
    {
        float2 binit = make_float2(bias, bias);
        double bd = *reinterpret_cast<double*>(&binit);
        accd[0] = bd; accd[1] = bd; accd[2] = bd; accd[3] = bd;
    }
#pragma unroll 4
    for (int k = 0; k < 64; k++) {
        float w = W[k * 192 + col];
        float2 wpair = make_float2(w, w);
        double wd = *reinterpret_cast<double*>(&wpair);
#pragma unroll
        for (int qd = 0; qd < 2; qd++) {
            double2 v = *reinterpret_cast<const double2*>(&sp[qd][off + k]);
            asm("fma.rn.f32x2 %0, %1, %2, %0;" : "+d"(accd[2 * qd]) : "d"(v.x), "d"(wd));
            asm("fma.rn.f32x2 %0, %1, %2, %0;" : "+d"(accd[2 * qd + 1]) : "d"(v.y), "d"(wd));
        }
    }
    int gidx = isI ? col : 192 + col;
#pragma unroll
    for (int p = 0; p < 4; p++) {
        float2 r = *reinterpret_cast<float2*>(&accd[p]);
        pg[2 * p][gidx] = r.x;
        pg[2 * p + 1][gidx] = r.y;
    }
    __syncthreads();

    for (int idx = t; idx < 512; idx += 384) {
        int node = idx >> 6, c = idx & 63;
        float r = sigf(pg[node][c] + pg[node][192 + c]);
        float z = sigf(pg[node][64 + c] + pg[node][256 + c]);
        float hv = reinterpret_cast<float*>(&sp[node >> 2][64 + c])[node & 3];
        float nn = tanhf(pg[node][128 + c] + r * pg[node][320 + c]);
        g_h[(n0 + node) * Dd + c] = (1.0f - z) * nn + z * hv;
    }
}

// ---------------- fused Set2Set (3 iters, online softmax) + MLP: 8 graphs/block ----------------
__global__ void __launch_bounds__(256) k_s2s(const float* __restrict__ b_ihl,
                                             const float* __restrict__ b_hhl,
                                             const float* __restrict__ b1,
                                             const float* __restrict__ W2,
                                             const float* __restrict__ b2,
                                             float* __restrict__ pred) {
    __shared__ float sq[8][128];
    __shared__ float shl[8][64];
    __shared__ float scl[8][64];
    __shared__ float pg[8][256];
    __shared__ float sy[8][64];
    int t = threadIdx.x;
    int g0 = blockIdx.x * 8;
    int wrp = t >> 5, lane = t & 31;

    for (int idx = t; idx < 1024; idx += 256) sq[idx >> 7][idx & 127] = 0.0f;
    for (int idx = t; idx < 512; idx += 256) {
        shl[idx >> 6][idx & 63] = 0.0f;
        scl[idx >> 6][idx & 63] = 0.0f;
    }
    int s = g_seg[g0 + wrp], en = g_seg[g0 + wrp + 1];
    float bias = b_ihl[t] + b_hhl[t];
    __syncthreads();

    for (int it = 0; it < 3; it++) {
        float acc[8];
#pragma unroll
        for (int g = 0; g < 8; g++) acc[g] = bias;
#pragma unroll 4
        for (int k = 0; k < 128; k++) {
            float w = g_Wtil[k * 256 + t];
#pragma unroll
            for (int g = 0; g < 8; g++) acc[g] += sq[g][k] * w;
        }
#pragma unroll 4
        for (int k = 0; k < 64; k++) {
            float w = g_Wthl[k * 256 + t];
#pragma unroll
            for (int g = 0; g < 8; g++) acc[g] += shl[g][k] * w;
        }
#pragma unroll
        for (int g = 0; g < 8; g++) pg[g][t] = acc[g];
        __syncthreads();

        for (int idx = t; idx < 512; idx += 256) {
            int g = idx >> 6, c = idx & 63;
            float cc = sigf(pg[g][64 + c]) * scl[g][c] + sigf(pg[g][c]) * tanhf(pg[g][128 + c]);
            float hh = sigf(pg[g][192 + c]) * tanhf(cc);
            scl[g][c] = cc;
            shl[g][c] = hh;
            sq[g][c] = hh;
        }
        __syncthreads();

        float h0 = shl[wrp][lane], h1 = shl[wrp][32 + lane];
        float m = -1e30f, ws = 0.f, r0 = 0.f, r1 = 0.f;
        for (int n = s; n < en; n++) {
            float va = g_h[n * Dd + lane], vb = g_h[n * Dd + 32 + lane];
            float v = va * h0 + vb * h1;
#pragma unroll
            for (int o = 16; o > 0; o >>= 1) v += __shfl_xor_sync(0xffffffffu, v, o);
            float mn = fmaxf(m, v);
            float sc = expf(m - mn);
            float ev = expf(v - mn);
            ws = ws * sc + ev;
            r0 = r0 * sc + ev * va;
            r1 = r1 * sc + ev * vb;
            m = mn;
        }
        if (en > s) {
            sq[wrp][64 + lane] = r0 / ws;
            sq[wrp][96 + lane] = r1 / ws;
        } else {
            sq[wrp][64 + lane] = 0.0f;
            sq[wrp][96 + lane] = 0.0f;
        }
        __syncthreads();
    }

    for (int idx = t; idx < 512; idx += 256) {
        int g = idx >> 6, c = idx & 63;
        float acc = b1[c];
#pragma unroll 8
        for (int k = 0; k < 128; k++) acc += sq[g][k] * g_Wt1[k * 64 + c];
        sy[g][c] = fmaxf(acc, 0.0f) * W2[c];
    }
    __syncthreads();
    float v = sy[wrp][lane] + sy[wrp][32 + lane];
#pragma unroll
    for (int o = 16; o > 0; o >>= 1) v += __shfl_xor_sync(0xffffffffu, v, o);
    if (lane == 0) pred[g0 + wrp] = v + b2[0];
}

// ---------------- launch ----------------
extern "C" void kernel_launch(void* const* d_in, const int* in_sizes, int n_in,
                              void* d_out, int out_size) {
    const float* x      = (const float*)d_in[0];
    const float* ea     = (const float*)d_in[1];
    const int*   ei     = (const int*)d_in[2];
    const int*   batch  = (const int*)d_in[3];
    const float* W0     = (const float*)d_in[4];
    const float* b0     = (const float*)d_in[5];
    const float* We1    = (const float*)d_in[6];
    const float* be1    = (const float*)d_in[7];
    const float* We2    = (const float*)d_in[8];
    const float* be2    = (const float*)d_in[9];
    const float* b_conv = (const float*)d_in[10];
    const float* W_ih   = (const float*)d_in[11];
    const float* W_hh   = (const float*)d_in[12];
    const float* b_ih   = (const float*)d_in[13];
    const float* b_hh   = (const float*)d_in[14];
    const float* W_ihl  = (const float*)d_in[15];
    const float* W_hhl  = (const float*)d_in[16];
    const float* b_ihl  = (const float*)d_in[17];
    const float* b_hhl  = (const float*)d_in[18];
    const float* W1     = (const float*)d_in[19];
    const float* b1     = (const float*)d_in[20];
    const float* W2     = (const float*)d_in[21];
    const float* b2     = (const float*)d_in[22];
    float* pred = (float*)d_out;

    k_setup1<<<(SETUP1_N + 255) / 256, 256>>>(W0, W_ih, W_hh, W_ihl, W_hhl, W1, We2);
    k_lin0cs<<<LIN0_BLKS + 161, 256>>>(x, b0, ei, batch);

    const int gemm_smem = 2 * 128 * SPAD * (int)sizeof(__nv_bfloat16);
    cudaFuncSetAttribute(k_gemm_tc2, cudaFuncAttributeMaxDynamicSharedMemorySize, gemm_smem);
    dim3 gg((Ee + 127) / 128, 2);
    k_gemm_tc2<<<gg, 256, gemm_smem>>>(be2, ea, We1, be1);

    for (int it = 0; it < 3; it++) {
        k_msg<<<(Ee + 7) / 8, 256>>>(ei);
        k_gru5<<<Nn / 8, 384>>>(b_ih, b_hh, b_conv);
    }

    k_s2s<<<Bb / 8, 256>>>(b_ihl, b_hhl, b1, W2, b2, pred);
}

// round 16
// speedup vs baseline: 1.0402x; 1.0402x over previous
#include <cuda_runtime.h>
#include <cuda_bf16.h>
#include <math.h>
#include <stdint.h>

#define Nn 20000
#define Ee 40000
#define Bb 1000
#define Ff 32
#define Dd 64
#define HE 128
#define DDm 4096

// ---------------- scratch ----------------
__device__ float g_h[Nn * Dd];
__device__ __nv_bfloat16 g_Wb[DDm * HE];
__device__ __nv_bfloat16 g_We[(size_t)Ee * DDm];
__device__ float g_agg[Nn * Dd];   // starts zeroed; every call leaves it zeroed again
__device__ float g_deg[Nn];
__device__ int   g_seg[Bb + 1];

// transposed weights [k][row]
__device__ float g_Wt0[Ff * Dd];
__device__ float g_Wti[Dd * 3 * Dd];
__device__ float g_Wth[Dd * 3 * Dd];
__device__ float g_Wtil[2 * Dd * 4 * Dd];
__device__ float g_Wthl[Dd * 4 * Dd];
__device__ float g_Wt1[2 * Dd * Dd];

__device__ __forceinline__ float sigf(float v) { return 1.0f / (1.0f + expf(-v)); }

// ---------------- setup 1: transpose + zero_deg + cvtW ----------------
__global__ void k_setup1(const float* __restrict__ W0, const float* __restrict__ W_ih,
                         const float* __restrict__ W_hh, const float* __restrict__ W_ihl,
                         const float* __restrict__ W_hhl, const float* __restrict__ W1,
                         const float* __restrict__ We2) {
    int i = blockIdx.x * blockDim.x + threadIdx.x;
    if (i < 2048) { int r = i / 32, k = i % 32; g_Wt0[k * 64 + r] = W0[i]; return; }
    i -= 2048;
    if (i < 12288) { int r = i / 64, k = i % 64; g_Wti[k * 192 + r] = W_ih[i]; return; }
    i -= 12288;
    if (i < 12288) { int r = i / 64, k = i % 64; g_Wth[k * 192 + r] = W_hh[i]; return; }
    i -= 12288;
    if (i < 32768) { int r = i / 128, k = i % 128; g_Wtil[k * 256 + r] = W_ihl[i]; return; }
    i -= 32768;
    if (i < 16384) { int r = i / 64, k = i % 64; g_Wthl[k * 256 + r] = W_hhl[i]; return; }
    i -= 16384;
    if (i < 8192) { int r = i / 128, k = i % 128; g_Wt1[k * 64 + r] = W1[i]; return; }
    i -= 8192;
    if (i < Nn) { g_deg[i] = 0.0f; return; }
    i -= Nn;
    if (i < DDm * HE) g_Wb[i] = __float2bfloat16(We2[i]);
}
#define SETUP1_N (83968 + Nn + DDm * HE)

// ---------------- lin0 (4 nodes/block) + degree count + segment starts ----------------
#define LIN0_BLKS 5000
__global__ void k_lin0cs(const float* __restrict__ x, const float* __restrict__ b0,
                         const int* __restrict__ ei, const int* __restrict__ batch) {
    int bid = blockIdx.x;
    int t = threadIdx.x;
    if (bid < LIN0_BLKS) {
        int n = bid * 4 + (t >> 6);
        int c = t & 63;
        __shared__ float sx[4][Ff];
        if (c < Ff) sx[t >> 6][c] = x[n * Ff + c];
        __syncthreads();
        float acc = b0[c];
#pragma unroll 8
        for (int k = 0; k < Ff; k++) acc += sx[t >> 6][k] * g_Wt0[k * 64 + c];
        g_h[n * Dd + c] = fmaxf(acc, 0.0f);
        return;
    }
    bid -= LIN0_BLKS;
    if (bid < 157) {
        int e = bid * 256 + t;
        if (e < Ee) atomicAdd(&g_deg[ei[Ee + e]], 1.0f);
    } else {
        int b = (bid - 157) * 256 + t;
        if (b > Bb) return;
        int lo = 0, hi = Nn;
        while (lo < hi) {
            int mid = (lo + hi) >> 1;
            if (batch[mid] < b) lo = mid + 1; else hi = mid;
        }
        g_seg[b] = lo;
    }
}

// ---------------- HMMA GEMM (round-14 proven, CTILES=8): dbuf B, 8 warps ----------------
#define SPAD 136
#define CTILES 8
__global__ void __launch_bounds__(256) k_gemm_tc2(const float* __restrict__ be2,
                                                  const float* __restrict__ ea,
                                                  const float* __restrict__ We1,
                                                  const float* __restrict__ be1) {
    extern __shared__ __nv_bfloat16 smem[];
    __nv_bfloat16* As  = smem;                    // [128][SPAD]
    __nv_bfloat16* Bs0 = smem + 128 * SPAD;
    __nv_bfloat16* Bs1 = Bs0 + 128 * SPAD;
    __shared__ float sea[128 * 5];
    __shared__ float sW1[128 * 5];
    __shared__ float sbe1[128];
    int row0 = blockIdx.x * 128;
    int colBase = blockIdx.y * (CTILES * 128);
    int tid = threadIdx.x;

    for (int idx = tid; idx < 640; idx += 256) {
        int r = idx / 5;
        sea[idx] = (row0 + r < Ee) ? ea[(size_t)(row0 + r) * 5 + (idx % 5)] : 0.0f;
        sW1[idx] = We1[idx];
    }
    if (tid < 128) sbe1[tid] = be1[tid];

    {
        for (int idx = tid; idx < 2048; idx += 256) {
            int r = idx >> 4, c = (idx & 15) * 8;
            const __nv_bfloat16* src = &g_Wb[(size_t)(colBase + r) * HE + c];
            uint32_t daddr = (uint32_t)__cvta_generic_to_shared(&Bs0[r * SPAD + c]);
            asm volatile("cp.async.cg.shared.global [%0], [%1], 16;\n" :: "r"(daddr), "l"(src));
        }
        asm volatile("cp.async.commit_group;\n");
    }
    __syncthreads();

    for (int idx = tid; idx < 2048; idx += 256) {
        int r = idx >> 4, c0 = (idx & 15) * 8;
        uint32_t pk[4];
#pragma unroll
        for (int cc = 0; cc < 8; cc += 2) {
            float a0 = sbe1[c0 + cc], a1 = sbe1[c0 + cc + 1];
#pragma unroll
            for (int j = 0; j < 5; j++) {
                float e = sea[r * 5 + j];
                a0 += e * sW1[(c0 + cc) * 5 + j];
                a1 += e * sW1[(c0 + cc + 1) * 5 + j];
            }
            __nv_bfloat162 bb = __float22bfloat162_rn(make_float2(fmaxf(a0, 0.f), fmaxf(a1, 0.f)));
            pk[cc >> 1] = *reinterpret_cast<uint32_t*>(&bb);
        }
        *(uint4*)&As[r * SPAD + c0] = *(uint4*)pk;
    }

    int wid = tid >> 5, lane = tid & 31;
    int wm = (wid >> 2) * 64;
    int wn = (wid & 3) * 32;
    int q = lane >> 3, r8 = lane & 7;

    for (int ct = 0; ct < CTILES; ct++) {
        __nv_bfloat16* Bcur = (ct & 1) ? Bs1 : Bs0;
        __nv_bfloat16* Bnxt = (ct & 1) ? Bs0 : Bs1;
        int col0 = colBase + ct * 128;

        if (ct + 1 < CTILES) {
            int coln = col0 + 128;
            for (int idx = tid; idx < 2048; idx += 256) {
                int r = idx >> 4, c = (idx & 15) * 8;
                const __nv_bfloat16* src = &g_Wb[(size_t)(coln + r) * HE + c];
                uint32_t daddr = (uint32_t)__cvta_generic_to_shared(&Bnxt[r * SPAD + c]);
                asm volatile("cp.async.cg.shared.global [%0], [%1], 16;\n" :: "r"(daddr), "l"(src));
            }
            asm volatile("cp.async.commit_group;\n");
            asm volatile("cp.async.wait_group 1;\n");
        } else {
            asm volatile("cp.async.wait_group 0;\n");
        }
        __syncthreads();

        float acc[4][4][4];
#pragma unroll
        for (int i = 0; i < 4; i++)
#pragma unroll
            for (int j = 0; j < 4; j++)
#pragma unroll
                for (int c = 0; c < 4; c++) acc[i][j][c] = 0.0f;

#pragma unroll
        for (int k0 = 0; k0 < 128; k0 += 16) {
            uint32_t a[4][4];
            uint32_t b[4][2];
#pragma unroll
            for (int mi = 0; mi < 4; mi++) {
                int m = wm + mi * 16 + ((q & 1) * 8) + r8;
                int k = k0 + ((q >> 1) * 8);
                uint32_t addr = (uint32_t)__cvta_generic_to_shared(&As[m * SPAD + k]);
                asm volatile("ldmatrix.sync.aligned.m8n8.x4.shared.b16 {%0,%1,%2,%3}, [%4];"
                             : "=r"(a[mi][0]), "=r"(a[mi][1]), "=r"(a[mi][2]), "=r"(a[mi][3])
                             : "r"(addr));
            }
#pragma unroll
            for (int np = 0; np < 2; np++) {
                int n = wn + np * 16 + ((q >> 1) * 8) + r8;
                int k = k0 + ((q & 1) * 8);
                uint32_t addr = (uint32_t)__cvta_generic_to_shared(&Bcur[n * SPAD + k]);
                asm volatile("ldmatrix.sync.aligned.m8n8.x4.shared.b16 {%0,%1,%2,%3}, [%4];"
                             : "=r"(b[np * 2][0]), "=r"(b[np * 2][1]),
                               "=r"(b[np * 2 + 1][0]), "=r"(b[np * 2 + 1][1])
                             : "r"(addr));
            }
#pragma unroll
            for (int mi = 0; mi < 4; mi++)
#pragma unroll
                for (int ni = 0; ni < 4; ni++) {
                    asm volatile(
                        "mma.sync.aligned.m16n8k16.row.col.f32.bf16.bf16.f32 "
                        "{%0,%1,%2,%3}, {%4,%5,%6,%7}, {%8,%9}, {%0,%1,%2,%3};"
                        : "+f"(acc[mi][ni][0]), "+f"(acc[mi][ni][1]),
                          "+f"(acc[mi][ni][2]), "+f"(acc[mi][ni][3])
                        : "r"(a[mi][0]), "r"(a[mi][1]), "r"(a[mi][2]), "r"(a[mi][3]),
                          "r"(b[ni][0]), "r"(b[ni][1]));
                }
        }
        __syncthreads();

#pragma unroll
        for (int mi = 0; mi < 4; mi++) {
            int rloc0 = wm + mi * 16 + (lane >> 2);
#pragma unroll
            for (int ni = 0; ni < 4; ni++) {
                int c = wn + ni * 8 + (lane & 3) * 2;
                float b0v = be2[col0 + c], b1v = be2[col0 + c + 1];
                *(__nv_bfloat162*)&Bcur[rloc0 * SPAD + c] =
                    __float22bfloat162_rn(make_float2(acc[mi][ni][0] + b0v, acc[mi][ni][1] + b1v));
                *(__nv_bfloat162*)&Bcur[(rloc0 + 8) * SPAD + c] =
                    __float22bfloat162_rn(make_float2(acc[mi][ni][2] + b0v, acc[mi][ni][3] + b1v));
            }
        }
        __syncthreads();

        for (int idx = tid; idx < 2048; idx += 256) {
            int r = idx >> 4, c = (idx & 15) * 8;
            if (row0 + r < Ee)
                *(uint4*)&g_We[(size_t)(row0 + r) * DDm + col0 + c] = *(const uint4*)&Bcur[r * SPAD + c];
        }
        __syncthreads();
    }
}

// ---------------- message + scatter ----------------
__global__ void k_msg(const int* __restrict__ ei) {
    int w = threadIdx.x >> 5;
    int e = blockIdx.x * 8 + w;
    int lane = threadIdx.x & 31;
    __shared__ float ss[8][Dd];
    if (e >= Ee) return;
    int src = ei[e], dst = ei[Ee + e];
    ss[w][lane] = g_h[src * Dd + lane];
    ss[w][lane + 32] = g_h[src * Dd + 32 + lane];
    __syncwarp();
    const __nv_bfloat162* W = (const __nv_bfloat162*)(g_We + (size_t)e * DDm);
    float a0 = 0.f, a1 = 0.f;
#pragma unroll
    for (int i = 0; i < Dd; i++) {
        float si = ss[w][i];
        float2 wf = __bfloat1622float2(W[i * 32 + lane]);
        a0 += si * wf.x;
        a1 += si * wf.y;
    }
    atomicAdd(&g_agg[dst * Dd + 2 * lane], a0);
    atomicAdd(&g_agg[dst * Dd + 2 * lane + 1], a1);
}

// ---------------- GRU v5: 8 nodes/block, float4-packed smem, f32x2 FMA ----------------
__global__ void __launch_bounds__(384) k_gru5(const float* __restrict__ b_ih,
                                              const float* __restrict__ b_hh,
                                              const float* __restrict__ b_conv) {
    __shared__ float4 sp[2][128];
    __shared__ float pg[8][384];
    int t = threadIdx.x;
    int n0 = blockIdx.x * 8;

    for (int i = t; i < 1024; i += 384) {
        int node = i >> 7, j = i & 127;
        int n = n0 + node;
        float val;
        if (j < 64) {
            float dg = fmaxf(g_deg[n], 1.0f);
            val = fmaxf(g_agg[n * Dd + j] / dg + b_conv[j], 0.0f);
            g_agg[n * Dd + j] = 0.0f;
        } else {
            val = g_h[n * Dd + (j - 64)];
        }
        reinterpret_cast<float*>(&sp[node >> 2][j])[node & 3] = val;
    }
    __syncthreads();

    bool isI = (t < 192);
    int col = isI ? t : t - 192;
    const float* W = isI ? g_Wti : g_Wth;
    int off = isI ? 0 : 64;
    float bias = isI ? b_ih[col] : b_hh[col];

    double accd[4];
    {
        float2 binit = make_float2(bias, bias);
        double bd = *reinterpret_cast<double*>(&binit);
        accd[0] = bd; accd[1] = bd; accd[2] = bd; accd[3] = bd;
    }
#pragma unroll 4
    for (int k = 0; k < 64; k++) {
        float w = W[k * 192 + col];
        float2 wpair = make_float2(w, w);
        double wd = *reinterpret_cast<double*>(&wpair);
#pragma unroll
        for (int qd = 0; qd < 2; qd++) {
            double2 v = *reinterpret_cast<const double2*>(&sp[qd][off + k]);
            asm("fma.rn.f32x2 %0, %1, %2, %0;" : "+d"(accd[2 * qd]) : "d"(v.x), "d"(wd));
            asm("fma.rn.f32x2 %0, %1, %2, %0;" : "+d"(accd[2 * qd + 1]) : "d"(v.y), "d"(wd));
        }
    }
    int gidx = isI ? col : 192 + col;
#pragma unroll
    for (int p = 0; p < 4; p++) {
        float2 r = *reinterpret_cast<float2*>(&accd[p]);
        pg[2 * p][gidx] = r.x;
        pg[2 * p + 1][gidx] = r.y;
    }
    __syncthreads();

    for (int idx = t; idx < 512; idx += 384) {
        int node = idx >> 6, c = idx & 63;
        float r = sigf(pg[node][c] + pg[node][192 + c]);
        float z = sigf(pg[node][64 + c] + pg[node][256 + c]);
        float hv = reinterpret_cast<float*>(&sp[node >> 2][64 + c])[node & 3];
        float nn = tanhf(pg[node][128 + c] + r * pg[node][320 + c]);
        g_h[(n0 + node) * Dd + c] = (1.0f - z) * nn + z * hv;
    }
}

// ---------------- fused Set2Set (3 iters, online softmax) + MLP: 8 graphs/block ----------------
__global__ void __launch_bounds__(256) k_s2s(const float* __restrict__ b_ihl,
                                             const float* __restrict__ b_hhl,
                                             const float* __restrict__ b1,
                                             const float* __restrict__ W2,
                                             const float* __restrict__ b2,
                                             float* __restrict__ pred) {
    __shared__ float sq[8][128];
    __shared__ float shl[8][64];
    __shared__ float scl[8][64];
    __shared__ float pg[8][256];
    __shared__ float sy[8][64];
    int t = threadIdx.x;
    int g0 = blockIdx.x * 8;
    int wrp = t >> 5, lane = t & 31;

    for (int idx = t; idx < 1024; idx += 256) sq[idx >> 7][idx & 127] = 0.0f;
    for (int idx = t; idx < 512; idx += 256) {
        shl[idx >> 6][idx & 63] = 0.0f;
        scl[idx >> 6][idx & 63] = 0.0f;
    }
    int s = g_seg[g0 + wrp], en = g_seg[g0 + wrp + 1];
    float bias = b_ihl[t] + b_hhl[t];
    __syncthreads();

    for (int it = 0; it < 3; it++) {
        float acc[8];
#pragma unroll
        for (int g = 0; g < 8; g++) acc[g] = bias;
#pragma unroll 4
        for (int k = 0; k < 128; k++) {
            float w = g_Wtil[k * 256 + t];
#pragma unroll
            for (int g = 0; g < 8; g++) acc[g] += sq[g][k] * w;
        }
#pragma unroll 4
        for (int k = 0; k < 64; k++) {
            float w = g_Wthl[k * 256 + t];
#pragma unroll
            for (int g = 0; g < 8; g++) acc[g] += shl[g][k] * w;
        }
#pragma unroll
        for (int g = 0; g < 8; g++) pg[g][t] = acc[g];
        __syncthreads();

        for (int idx = t; idx < 512; idx += 256) {
            int g = idx >> 6, c = idx & 63;
            float cc = sigf(pg[g][64 + c]) * scl[g][c] + sigf(pg[g][c]) * tanhf(pg[g][128 + c]);
            float hh = sigf(pg[g][192 + c]) * tanhf(cc);
            scl[g][c] = cc;
            shl[g][c] = hh;
            sq[g][c] = hh;
        }
        __syncthreads();

        float h0 = shl[wrp][lane], h1 = shl[wrp][32 + lane];
        float m = -1e30f, ws = 0.f, r0 = 0.f, r1 = 0.f;
        for (int n = s; n < en; n++) {
            float va = g_h[n * Dd + lane], vb = g_h[n * Dd + 32 + lane];
            float v = va * h0 + vb * h1;
#pragma unroll
            for (int o = 16; o > 0; o >>= 1) v += __shfl_xor_sync(0xffffffffu, v, o);
            float mn = fmaxf(m, v);
            float sc = expf(m - mn);
            float ev = expf(v - mn);
            ws = ws * sc + ev;
            r0 = r0 * sc + ev * va;
            r1 = r1 * sc + ev * vb;
            m = mn;
        }
        if (en > s) {
            sq[wrp][64 + lane] = r0 / ws;
            sq[wrp][96 + lane] = r1 / ws;
        } else {
            sq[wrp][64 + lane] = 0.0f;
            sq[wrp][96 + lane] = 0.0f;
        }
        __syncthreads();
    }

    for (int idx = t; idx < 512; idx += 256) {
        int g = idx >> 6, c = idx & 63;
        float acc = b1[c];
#pragma unroll 8
        for (int k = 0; k < 128; k++) acc += sq[g][k] * g_Wt1[k * 64 + c];
        sy[g][c] = fmaxf(acc, 0.0f) * W2[c];
    }
    __syncthreads();
    float v = sy[wrp][lane] + sy[wrp][32 + lane];
#pragma unroll
    for (int o = 16; o > 0; o >>= 1) v += __shfl_xor_sync(0xffffffffu, v, o);
    if (lane == 0) pred[g0 + wrp] = v + b2[0];
}

// ---------------- launch ----------------
extern "C" void kernel_launch(void* const* d_in, const int* in_sizes, int n_in,
                              void* d_out, int out_size) {
    const float* x      = (const float*)d_in[0];
    const float* ea     = (const float*)d_in[1];
    const int*   ei     = (const int*)d_in[2];
    const int*   batch  = (const int*)d_in[3];
    const float* W0     = (const float*)d_in[4];
    const float* b0     = (const float*)d_in[5];
    const float* We1    = (const float*)d_in[6];
    const float* be1    = (const float*)d_in[7];
    const float* We2    = (const float*)d_in[8];
    const float* be2    = (const float*)d_in[9];
    const float* b_conv = (const float*)d_in[10];
    const float* W_ih   = (const float*)d_in[11];
    const float* W_hh   = (const float*)d_in[12];
    const float* b_ih   = (const float*)d_in[13];
    const float* b_hh   = (const float*)d_in[14];
    const float* W_ihl  = (const float*)d_in[15];
    const float* W_hhl  = (const float*)d_in[16];
    const float* b_ihl  = (const float*)d_in[17];
    const float* b_hhl  = (const float*)d_in[18];
    const float* W1     = (const float*)d_in[19];
    const float* b1     = (const float*)d_in[20];
    const float* W2     = (const float*)d_in[21];
    const float* b2     = (const float*)d_in[22];
    float* pred = (float*)d_out;

    k_setup1<<<(SETUP1_N + 255) / 256, 256>>>(W0, W_ih, W_hh, W_ihl, W_hhl, W1, We2);
    k_lin0cs<<<LIN0_BLKS + 161, 256>>>(x, b0, ei, batch);

    const int gemm_smem = 3 * 128 * SPAD * (int)sizeof(__nv_bfloat16);
    cudaFuncSetAttribute(k_gemm_tc2, cudaFuncAttributeMaxDynamicSharedMemorySize, gemm_smem);
    dim3 gg((Ee + 127) / 128, DDm / (CTILES * 128));
    k_gemm_tc2<<<gg, 256, gemm_smem>>>(be2, ea, We1, be1);

    for (int it = 0; it < 3; it++) {
        k_msg<<<(Ee + 7) / 8, 256>>>(ei);
        k_gru5<<<Nn / 8, 384>>>(b_ih, b_hh, b_conv);
    }

    k_s2s<<<Bb / 8, 256>>>(b_ihl, b_hhl, b1, W2, b2, pred);
}